// round 1
// baseline (speedup 1.0000x reference)
#include <cuda_runtime.h>
#include <cuda_bf16.h>
#include <cstdint>
#include <cstddef>

// Problem constants
#define Bc 4
#define Nn 2048
#define Cc 1024
#define Hh 16
#define Dd 64
#define Mrows (Bc * Nn)   // 8192
#define KDIM  Cc          // 1024

// Scratch (static device allocations are allowed)
__device__ float g_qkv[(size_t)3 * Bc * Hh * Nn * Dd];   // [3][B][H][N][D]
__device__ float g_att[(size_t)Mrows * Cc];              // [B][N][C], c = h*D+d

// ---------------------------------------------------------------------------
// SGEMM: out[m,n] = sum_k A[m,k] * W[n,k]   (A row-major [M,K], W row-major [NCOLS,K])
// 128x128 tile, BK=8, 256 threads, 8x8 per-thread register tile.
// MODE 0: A = x, scatter into g_qkv layout [3][B][H][N][D]
// MODE 1: A = g_att, out[m*NCOLS+n] = acc + bias[n]
// ---------------------------------------------------------------------------
template<int NCOLS, int MODE>
__global__ void __launch_bounds__(256, 2) sgemm_kernel(
    const float* __restrict__ A,
    const float* __restrict__ W,
    const float* __restrict__ bias,
    float* __restrict__ out)
{
    __shared__ float As[8][128];
    __shared__ float Bs[8][128];

    const float* Asrc = (MODE == 0) ? A : (const float*)g_att;

    const int bx = blockIdx.x;   // n tile
    const int by = blockIdx.y;   // m tile
    const int tid = threadIdx.x;
    const int tx = tid & 15;
    const int ty = tid >> 4;

    const int lr = tid >> 1;          // 0..127 (load row within tile)
    const int lc = (tid & 1) << 2;    // 0 or 4 (k offset of float4)

    const float* Ab = Asrc + (size_t)(by * 128 + lr) * KDIM + lc;
    const float* Wb = W    + (size_t)(bx * 128 + lr) * KDIM + lc;

    float acc[8][8];
#pragma unroll
    for (int i = 0; i < 8; i++)
#pragma unroll
        for (int j = 0; j < 8; j++) acc[i][j] = 0.f;

    for (int k0 = 0; k0 < KDIM; k0 += 8) {
        float4 av = *(const float4*)(Ab + k0);
        float4 wv = *(const float4*)(Wb + k0);
        As[lc + 0][lr] = av.x;
        As[lc + 1][lr] = av.y;
        As[lc + 2][lr] = av.z;
        As[lc + 3][lr] = av.w;
        Bs[lc + 0][lr] = wv.x;
        Bs[lc + 1][lr] = wv.y;
        Bs[lc + 2][lr] = wv.z;
        Bs[lc + 3][lr] = wv.w;
        __syncthreads();

#pragma unroll
        for (int kk = 0; kk < 8; kk++) {
            float ar[8], br[8];
            *(float4*)&ar[0] = *(const float4*)&As[kk][ty * 8];
            *(float4*)&ar[4] = *(const float4*)&As[kk][ty * 8 + 4];
            *(float4*)&br[0] = *(const float4*)&Bs[kk][tx * 8];
            *(float4*)&br[4] = *(const float4*)&Bs[kk][tx * 8 + 4];
#pragma unroll
            for (int i = 0; i < 8; i++)
#pragma unroll
                for (int j = 0; j < 8; j++)
                    acc[i][j] = fmaf(ar[i], br[j], acc[i][j]);
        }
        __syncthreads();
    }

    const int m0 = by * 128 + ty * 8;
    const int n0 = bx * 128 + tx * 8;
#pragma unroll
    for (int i = 0; i < 8; i++) {
        const int m = m0 + i;
        const int b = m / Nn;
        const int row = m % Nn;
#pragma unroll
        for (int j = 0; j < 8; j++) {
            const int n = n0 + j;
            if (MODE == 0) {
                // n = t3*1024 + h*64 + d
                const int t3 = n >> 10;
                const int rem = n & 1023;
                const int h = rem >> 6;
                const int d = rem & 63;
                g_qkv[(((size_t)(t3 * Bc + b) * Hh + h) * Nn + row) * Dd + d] = acc[i][j];
            } else {
                out[(size_t)m * NCOLS + n] = acc[i][j] + bias[n];
            }
        }
    }
}

// ---------------------------------------------------------------------------
// Flash attention (fp32, online softmax).
// grid = (N/64, H, B), block = 256.
// Per block: 64 queries; loop over key tiles of 64. smem stride 65 (bank-safe).
// ---------------------------------------------------------------------------
#define SD 65
#define FLASH_SMEM_FLOATS (4 * 64 * SD + 3 * 64)
#define FLASH_SMEM_BYTES  (FLASH_SMEM_FLOATS * 4)

__global__ void __launch_bounds__(256, 3) flash_kernel()
{
    extern __shared__ float sm[];
    float* Qs   = sm;                 // 64 x 65
    float* Ks   = Qs + 64 * SD;       // 64 x 65
    float* Vs   = Ks + 64 * SD;       // 64 x 65
    float* Ss   = Vs + 64 * SD;       // 64 x 65
    float* mrow = Ss + 64 * SD;       // 64
    float* lrow = mrow + 64;          // 64
    float* crow = lrow + 64;          // 64

    const int qt = blockIdx.x;   // query tile
    const int h  = blockIdx.y;
    const int b  = blockIdx.z;
    const int tid = threadIdx.x;
    const int tx = tid & 15;     // output d group
    const int ty = tid >> 4;     // output q group

    const float* qptr = g_qkv + ((size_t)(0 * Bc + b) * Hh + h) * Nn * Dd;
    const float* kptr = g_qkv + ((size_t)(1 * Bc + b) * Hh + h) * Nn * Dd;
    const float* vptr = g_qkv + ((size_t)(2 * Bc + b) * Hh + h) * Nn * Dd;

    // Load Q tile (64 rows x 64 cols)
#pragma unroll
    for (int i = 0; i < 4; i++) {
        const int f4 = tid + i * 256;       // 0..1023
        const int r  = f4 >> 4;
        const int cg = (f4 & 15) << 2;
        float4 v = *(const float4*)(qptr + (size_t)(qt * 64 + r) * Dd + cg);
        Qs[r * SD + cg + 0] = v.x;
        Qs[r * SD + cg + 1] = v.y;
        Qs[r * SD + cg + 2] = v.z;
        Qs[r * SD + cg + 3] = v.w;
    }
    if (tid < 64) { mrow[tid] = -1e30f; lrow[tid] = 0.f; }

    float acc[4][4];
#pragma unroll
    for (int i = 0; i < 4; i++)
#pragma unroll
        for (int j = 0; j < 4; j++) acc[i][j] = 0.f;

    __syncthreads();

    for (int kt = 0; kt < Nn / 64; kt++) {
        // Load K and V tiles
#pragma unroll
        for (int i = 0; i < 4; i++) {
            const int f4 = tid + i * 256;
            const int r  = f4 >> 4;
            const int cg = (f4 & 15) << 2;
            float4 kv = *(const float4*)(kptr + (size_t)(kt * 64 + r) * Dd + cg);
            float4 vv = *(const float4*)(vptr + (size_t)(kt * 64 + r) * Dd + cg);
            Ks[r * SD + cg + 0] = kv.x;
            Ks[r * SD + cg + 1] = kv.y;
            Ks[r * SD + cg + 2] = kv.z;
            Ks[r * SD + cg + 3] = kv.w;
            Vs[r * SD + cg + 0] = vv.x;
            Vs[r * SD + cg + 1] = vv.y;
            Vs[r * SD + cg + 2] = vv.z;
            Vs[r * SD + cg + 3] = vv.w;
        }
        __syncthreads();

        // S = Q @ K^T (4x4 per thread)
        float s[4][4];
#pragma unroll
        for (int i = 0; i < 4; i++)
#pragma unroll
            for (int j = 0; j < 4; j++) s[i][j] = 0.f;

#pragma unroll 8
        for (int k = 0; k < 64; k++) {
            float qa[4], kb[4];
#pragma unroll
            for (int i = 0; i < 4; i++) qa[i] = Qs[(ty * 4 + i) * SD + k];
#pragma unroll
            for (int j = 0; j < 4; j++) kb[j] = Ks[(tx * 4 + j) * SD + k];
#pragma unroll
            for (int i = 0; i < 4; i++)
#pragma unroll
                for (int j = 0; j < 4; j++)
                    s[i][j] = fmaf(qa[i], kb[j], s[i][j]);
        }
#pragma unroll
        for (int i = 0; i < 4; i++)
#pragma unroll
            for (int j = 0; j < 4; j++)
                Ss[(ty * 4 + i) * SD + tx * 4 + j] = s[i][j] * 0.125f;
        __syncthreads();

        // Online softmax: one thread per query row
        if (tid < 64) {
            const int r = tid;
            float mold = mrow[r];
            float mx = mold;
#pragma unroll 8
            for (int c = 0; c < 64; c++) mx = fmaxf(mx, Ss[r * SD + c]);
            const float corr = __expf(mold - mx);
            float ls = 0.f;
#pragma unroll 8
            for (int c = 0; c < 64; c++) {
                const float p = __expf(Ss[r * SD + c] - mx);
                Ss[r * SD + c] = p;
                ls += p;
            }
            lrow[r] = lrow[r] * corr + ls;
            mrow[r] = mx;
            crow[r] = corr;
        }
        __syncthreads();

        // Rescale accumulators and accumulate P @ V
#pragma unroll
        for (int i = 0; i < 4; i++) {
            const float cf = crow[ty * 4 + i];
#pragma unroll
            for (int j = 0; j < 4; j++) acc[i][j] *= cf;
        }
#pragma unroll 8
        for (int k = 0; k < 64; k++) {
            float pv[4], vv[4];
#pragma unroll
            for (int i = 0; i < 4; i++) pv[i] = Ss[(ty * 4 + i) * SD + k];
#pragma unroll
            for (int j = 0; j < 4; j++) vv[j] = Vs[k * SD + tx * 4 + j];
#pragma unroll
            for (int i = 0; i < 4; i++)
#pragma unroll
                for (int j = 0; j < 4; j++)
                    acc[i][j] = fmaf(pv[i], vv[j], acc[i][j]);
        }
        __syncthreads();  // before next tile overwrites K/V/S
    }

    // Normalize and write to g_att[B][N][C] with c = h*64 + d
#pragma unroll
    for (int i = 0; i < 4; i++) {
        const float inv = 1.f / lrow[ty * 4 + i];
        const int row = qt * 64 + ty * 4 + i;
#pragma unroll
        for (int j = 0; j < 4; j++) {
            g_att[((size_t)b * Nn + row) * Cc + h * 64 + tx * 4 + j] = acc[i][j] * inv;
        }
    }
}

// ---------------------------------------------------------------------------
// Launch
// ---------------------------------------------------------------------------
extern "C" void kernel_launch(void* const* d_in, const int* in_sizes, int n_in,
                              void* d_out, int out_size)
{
    // Identify inputs by element count (robust to ordering)
    const float* x = nullptr;      // 8388608
    const float* Wqkv = nullptr;   // 3145728
    const float* Wproj = nullptr;  // 1048576
    const float* bproj = nullptr;  // 1024
    for (int i = 0; i < n_in; i++) {
        switch (in_sizes[i]) {
            case 8388608: x = (const float*)d_in[i]; break;
            case 3145728: Wqkv = (const float*)d_in[i]; break;
            case 1048576: Wproj = (const float*)d_in[i]; break;
            case 1024:    bproj = (const float*)d_in[i]; break;
            default: break;
        }
    }
    float* out = (float*)d_out;

    // 1) QKV projection: [8192,1024] @ [3072,1024]^T -> scatter to g_qkv
    dim3 g1(3 * Cc / 128, Mrows / 128);   // (24, 64)
    sgemm_kernel<3 * Cc, 0><<<g1, 256>>>(x, Wqkv, nullptr, nullptr);

    // 2) Flash attention
    cudaFuncSetAttribute(flash_kernel,
                         cudaFuncAttributeMaxDynamicSharedMemorySize,
                         FLASH_SMEM_BYTES);
    flash_kernel<<<dim3(Nn / 64, Hh, Bc), 256, FLASH_SMEM_BYTES>>>();

    // 3) Output projection + bias: [8192,1024] @ [1024,1024]^T + b -> out
    dim3 g2(Cc / 128, Mrows / 128);       // (8, 64)
    sgemm_kernel<Cc, 1><<<g2, 256>>>(nullptr, Wproj, bproj, out);
}

// round 2
// speedup vs baseline: 3.7307x; 3.7307x over previous
#include <cuda_runtime.h>
#include <cstdint>
#include <cstddef>

#define Bc 4
#define Nn 2048
#define Cc 1024
#define Hh 16
#define Dd 64
#define Mrows (Bc * Nn)   // 8192
#define KDIM  Cc          // 1024
#define BK 32
#define SA 36             // gemm smem row stride (floats): bank-conflict-free frags

// Scratch
__device__ float g_qkv[(size_t)3 * Bc * Hh * Nn * Dd];  // [3][B][H][N][D], tf32-rounded
__device__ float g_att[(size_t)Mrows * Cc];             // [B][N][C], tf32-rounded
__device__ float g_x [(size_t)Mrows * Cc];              // tf32-rounded copy of x
__device__ float g_w1[(size_t)3 * Cc * Cc];             // tf32-rounded W_qkv
__device__ float g_w2[(size_t)Cc * Cc];                 // tf32-rounded W_proj

// ---------------------------------------------------------------------------
// helpers
// ---------------------------------------------------------------------------
__device__ __forceinline__ float tf32r(float x) {
    uint32_t u;
    asm("cvt.rna.tf32.f32 %0, %1;" : "=r"(u) : "f"(x));
    return __uint_as_float(u);
}

__device__ __forceinline__ void cp16(float* dst, const float* src) {
    uint32_t d = (uint32_t)__cvta_generic_to_shared(dst);
    asm volatile("cp.async.cg.shared.global [%0], [%1], 16;\n" :: "r"(d), "l"(src));
}
#define CP_COMMIT asm volatile("cp.async.commit_group;\n")
template<int N> __device__ __forceinline__ void cp_wait() {
    asm volatile("cp.async.wait_group %0;\n" :: "n"(N));
}

__device__ __forceinline__ void mma_tf32(float c[4], const uint32_t a[4], const uint32_t b[2]) {
    asm volatile(
        "mma.sync.aligned.m16n8k8.row.col.f32.tf32.tf32.f32 "
        "{%0,%1,%2,%3},{%4,%5,%6,%7},{%8,%9},{%0,%1,%2,%3};"
        : "+f"(c[0]), "+f"(c[1]), "+f"(c[2]), "+f"(c[3])
        : "r"(a[0]), "r"(a[1]), "r"(a[2]), "r"(a[3]), "r"(b[0]), "r"(b[1]));
}

// ---------------------------------------------------------------------------
// tf32 pre-rounding (RNA) of inputs into scratch
// ---------------------------------------------------------------------------
__global__ void round_kernel(const float* __restrict__ s, float* __restrict__ d, int n4) {
    int i = blockIdx.x * blockDim.x + threadIdx.x;
    if (i < n4) {
        float4 v = ((const float4*)s)[i];
        v.x = tf32r(v.x); v.y = tf32r(v.y); v.z = tf32r(v.z); v.w = tf32r(v.w);
        ((float4*)d)[i] = v;
    }
}

// ---------------------------------------------------------------------------
// tf32 GEMM: out[m,n] = sum_k A[m,k]*W[n,k]. 128x128 tile, BK=32, 3-stage cp.async.
// 8 warps (4m x 2n), warp tile 32x64, mma m16n8k8.
// MODE 0: A=g_x, W=g_w1, scatter tf32-rounded into g_qkv [3][B][H][N][D]
// MODE 1: A=g_att, W=g_w2, out = acc + bias (final fp32 output)
// ---------------------------------------------------------------------------
template<int NCOLS, int MODE>
__global__ void __launch_bounds__(256) mm_kernel(const float* __restrict__ bias,
                                                 float* __restrict__ out)
{
    extern __shared__ float smem[];
    float* As = smem;                 // [3][128*SA]
    float* Bs = smem + 3 * 128 * SA;  // [3][128*SA]
    const float* A = (MODE == 0) ? g_x : g_att;
    const float* W = (MODE == 0) ? g_w1 : g_w2;

    const int bx = blockIdx.x, by = blockIdx.y;
    const int tid = threadIdx.x;
    const int w = tid >> 5, lane = tid & 31;
    const int wm = w & 3, wn = w >> 2;
    const int r = lane >> 2, c = lane & 3;

    float acc[2][8][4];
#pragma unroll
    for (int mt = 0; mt < 2; mt++)
#pragma unroll
        for (int nt = 0; nt < 8; nt++)
#pragma unroll
            for (int j = 0; j < 4; j++) acc[mt][nt][j] = 0.f;

    // stage loader: 256 threads x 4 chunks of 16B per operand
#define LOAD_STAGE(s, k0)                                                        \
    {                                                                            \
        float* as = As + (s) * 128 * SA;                                         \
        float* bs = Bs + (s) * 128 * SA;                                         \
        _Pragma("unroll")                                                        \
        for (int i = 0; i < 4; i++) {                                            \
            int id = tid + i * 256;                                              \
            int row = id >> 3, cg = (id & 7) << 2;                               \
            cp16(as + row * SA + cg, A + (size_t)(by * 128 + row) * KDIM + (k0) + cg); \
            cp16(bs + row * SA + cg, W + (size_t)(bx * 128 + row) * KDIM + (k0) + cg); \
        }                                                                        \
    }

    LOAD_STAGE(0, 0); CP_COMMIT;
    LOAD_STAGE(1, BK); CP_COMMIT;

    const int NT = KDIM / BK;  // 32
    for (int t = 0; t < NT; t++) {
        cp_wait<1>();
        __syncthreads();
        if (t + 2 < NT) LOAD_STAGE((t + 2) % 3, (t + 2) * BK);
        CP_COMMIT;

        const float* as = As + (t % 3) * 128 * SA;
        const float* bs = Bs + (t % 3) * 128 * SA;
#pragma unroll
        for (int kk = 0; kk < 4; kk++) {
            uint32_t af[2][4];
#pragma unroll
            for (int mt = 0; mt < 2; mt++) {
                const float* ap = as + (wm * 32 + mt * 16 + r) * SA + kk * 8 + c;
                af[mt][0] = __float_as_uint(ap[0]);
                af[mt][1] = __float_as_uint(ap[8 * SA]);
                af[mt][2] = __float_as_uint(ap[4]);
                af[mt][3] = __float_as_uint(ap[8 * SA + 4]);
            }
#pragma unroll
            for (int nt = 0; nt < 8; nt++) {
                const float* bp = bs + (wn * 64 + nt * 8 + r) * SA + kk * 8 + c;
                uint32_t bf[2] = { __float_as_uint(bp[0]), __float_as_uint(bp[4]) };
                mma_tf32(acc[0][nt], af[0], bf);
                mma_tf32(acc[1][nt], af[1], bf);
            }
        }
        __syncthreads();
    }
#undef LOAD_STAGE

    // epilogue
#pragma unroll
    for (int mt = 0; mt < 2; mt++) {
#pragma unroll
        for (int i2 = 0; i2 < 2; i2++) {
            const int m = by * 128 + wm * 32 + mt * 16 + r + i2 * 8;
            const int bidx = m >> 11;        // / 2048
            const int row  = m & 2047;
#pragma unroll
            for (int nt = 0; nt < 8; nt++) {
                const int n = bx * 128 + wn * 64 + nt * 8 + 2 * c;
                float v0 = acc[mt][nt][i2 * 2 + 0];
                float v1 = acc[mt][nt][i2 * 2 + 1];
                if (MODE == 0) {
                    const int t3 = n >> 10, rem = n & 1023;
                    const int hh = rem >> 6, d = rem & 63;
                    float2 p = make_float2(tf32r(v0), tf32r(v1));
                    *(float2*)&g_qkv[(((size_t)(t3 * Bc + bidx) * Hh + hh) * Nn + row) * Dd + d] = p;
                } else {
                    float2 bb = *(const float2*)&bias[n];
                    *(float2*)&out[(size_t)m * NCOLS + n] = make_float2(v0 + bb.x, v1 + bb.y);
                }
            }
        }
    }
}

// ---------------------------------------------------------------------------
// Flash attention, tf32 mma. BQ=128, BK=64, 256 threads (8 warps x 16 rows).
// K/V double-buffered via cp.async. Online softmax on mma fragments.
// ---------------------------------------------------------------------------
#define QS 68   // Q/P smem stride (4 mod 32 -> conflict-free A/K frags)
#define KS 68
#define VS 72   // (8 mod 32 -> conflict-free V frags)
#define FLASH_SMEM_BYTES ((128*QS + 128*QS + 2*64*KS + 2*64*VS) * 4)

__global__ void __launch_bounds__(256) flash_kernel()
{
    extern __shared__ float sm[];
    float* Qs = sm;                    // 128 x QS
    float* Ps = Qs + 128 * QS;         // 128 x QS
    float* Ks = Ps + 128 * QS;         // 2 x 64 x KS
    float* Vs = Ks + 2 * 64 * KS;      // 2 x 64 x VS

    const int qt = blockIdx.x, h = blockIdx.y, b = blockIdx.z;
    const int tid = threadIdx.x;
    const int w = tid >> 5, lane = tid & 31;
    const int r = lane >> 2, c = lane & 3;

    const float* qptr = g_qkv + ((size_t)(0 * Bc + b) * Hh + h) * Nn * Dd + (size_t)qt * 128 * Dd;
    const float* kptr = g_qkv + ((size_t)(1 * Bc + b) * Hh + h) * Nn * Dd;
    const float* vptr = g_qkv + ((size_t)(2 * Bc + b) * Hh + h) * Nn * Dd;

    // load Q tile (128 x 64)
#pragma unroll
    for (int i = 0; i < 8; i++) {
        int id = tid + i * 256;
        int qr = id >> 4, cg = (id & 15) << 2;
        float4 v = *(const float4*)(qptr + (size_t)qr * 64 + cg);
        Qs[qr * QS + cg + 0] = v.x;
        Qs[qr * QS + cg + 1] = v.y;
        Qs[qr * QS + cg + 2] = v.z;
        Qs[qr * QS + cg + 3] = v.w;
    }

#define KV_LOAD(kt, buf)                                                        \
    {                                                                           \
        _Pragma("unroll")                                                       \
        for (int i = 0; i < 4; i++) {                                           \
            int id = tid + i * 256;                                             \
            int kr = id >> 4, cg = (id & 15) << 2;                              \
            cp16(Ks + (buf) * 64 * KS + kr * KS + cg,                           \
                 kptr + (size_t)((kt) * 64 + kr) * 64 + cg);                    \
            cp16(Vs + (buf) * 64 * VS + kr * VS + cg,                           \
                 vptr + (size_t)((kt) * 64 + kr) * 64 + cg);                    \
        }                                                                       \
    }

    KV_LOAD(0, 0); CP_COMMIT;

    float o[8][4];
#pragma unroll
    for (int nt = 0; nt < 8; nt++)
#pragma unroll
        for (int j = 0; j < 4; j++) o[nt][j] = 0.f;
    float m0 = -1e30f, m1 = -1e30f, l0 = 0.f, l1 = 0.f;
    const float ct = 0.125f * 1.4426950408889634f;  // scale * log2(e)
    const int qrow = w * 16 + r;

    for (int kt = 0; kt < Nn / 64; kt++) {
        if (kt + 1 < Nn / 64) KV_LOAD(kt + 1, (kt + 1) & 1);
        CP_COMMIT;
        cp_wait<1>();
        __syncthreads();

        const float* Kb = Ks + (kt & 1) * 64 * KS;
        const float* Vb = Vs + (kt & 1) * 64 * VS;

        // S = Q @ K^T  (raw scores)
        float s[8][4];
#pragma unroll
        for (int nt = 0; nt < 8; nt++)
#pragma unroll
            for (int j = 0; j < 4; j++) s[nt][j] = 0.f;

#pragma unroll
        for (int kk = 0; kk < 8; kk++) {
            uint32_t a[4];
            const float* ap = Qs + qrow * QS + kk * 8 + c;
            a[0] = __float_as_uint(ap[0]);
            a[1] = __float_as_uint(ap[8 * QS]);
            a[2] = __float_as_uint(ap[4]);
            a[3] = __float_as_uint(ap[8 * QS + 4]);
#pragma unroll
            for (int nt = 0; nt < 8; nt++) {
                const float* bp = Kb + (nt * 8 + r) * KS + kk * 8 + c;
                uint32_t bf[2] = { __float_as_uint(bp[0]), __float_as_uint(bp[4]) };
                mma_tf32(s[nt], a, bf);
            }
        }

        // online softmax on fragments (rows qrow and qrow+8)
        float mx0 = -1e30f, mx1 = -1e30f;
#pragma unroll
        for (int nt = 0; nt < 8; nt++) {
            mx0 = fmaxf(mx0, fmaxf(s[nt][0], s[nt][1]));
            mx1 = fmaxf(mx1, fmaxf(s[nt][2], s[nt][3]));
        }
        mx0 = fmaxf(mx0, __shfl_xor_sync(0xffffffff, mx0, 1));
        mx0 = fmaxf(mx0, __shfl_xor_sync(0xffffffff, mx0, 2));
        mx1 = fmaxf(mx1, __shfl_xor_sync(0xffffffff, mx1, 1));
        mx1 = fmaxf(mx1, __shfl_xor_sync(0xffffffff, mx1, 2));

        const float nm0 = fmaxf(m0, mx0), nm1 = fmaxf(m1, mx1);
        const float cor0 = exp2f((m0 - nm0) * ct);
        const float cor1 = exp2f((m1 - nm1) * ct);
        m0 = nm0; m1 = nm1;

        float ls0 = 0.f, ls1 = 0.f;
#pragma unroll
        for (int nt = 0; nt < 8; nt++) {
            s[nt][0] = exp2f((s[nt][0] - nm0) * ct);
            s[nt][1] = exp2f((s[nt][1] - nm0) * ct);
            s[nt][2] = exp2f((s[nt][2] - nm1) * ct);
            s[nt][3] = exp2f((s[nt][3] - nm1) * ct);
            ls0 += s[nt][0] + s[nt][1];
            ls1 += s[nt][2] + s[nt][3];
        }
        ls0 += __shfl_xor_sync(0xffffffff, ls0, 1);
        ls0 += __shfl_xor_sync(0xffffffff, ls0, 2);
        ls1 += __shfl_xor_sync(0xffffffff, ls1, 1);
        ls1 += __shfl_xor_sync(0xffffffff, ls1, 2);
        l0 = l0 * cor0 + ls0;
        l1 = l1 * cor1 + ls1;

#pragma unroll
        for (int nt = 0; nt < 8; nt++) {
            o[nt][0] *= cor0; o[nt][1] *= cor0;
            o[nt][2] *= cor1; o[nt][3] *= cor1;
        }

        // P -> smem (tf32-rounded)
#pragma unroll
        for (int nt = 0; nt < 8; nt++) {
            const int col = nt * 8 + 2 * c;
            *(float2*)&Ps[qrow * QS + col]       = make_float2(tf32r(s[nt][0]), tf32r(s[nt][1]));
            *(float2*)&Ps[(qrow + 8) * QS + col] = make_float2(tf32r(s[nt][2]), tf32r(s[nt][3]));
        }
        __syncwarp();

        // O += P @ V
#pragma unroll
        for (int kk = 0; kk < 8; kk++) {
            uint32_t a[4];
            const float* ap = Ps + qrow * QS + kk * 8 + c;
            a[0] = __float_as_uint(ap[0]);
            a[1] = __float_as_uint(ap[8 * QS]);
            a[2] = __float_as_uint(ap[4]);
            a[3] = __float_as_uint(ap[8 * QS + 4]);
#pragma unroll
            for (int nt = 0; nt < 8; nt++) {
                const float* bp = Vb + (kk * 8 + c) * VS + nt * 8 + r;
                uint32_t bf[2] = { __float_as_uint(bp[0]), __float_as_uint(bp[4 * VS]) };
                mma_tf32(o[nt], a, bf);
            }
        }
        __syncthreads();  // protect K/V buffer about to be overwritten
    }
#undef KV_LOAD

    // finalize: normalize, tf32-round (feeds proj GEMM), write g_att
    const float i0 = 1.f / l0, i1 = 1.f / l1;
    const int grow = qt * 128 + qrow;
    float* ob = g_att + ((size_t)b * Nn) * Cc + (size_t)h * 64;
#pragma unroll
    for (int nt = 0; nt < 8; nt++) {
        const int col = nt * 8 + 2 * c;
        *(float2*)&ob[(size_t)grow * Cc + col] =
            make_float2(tf32r(o[nt][0] * i0), tf32r(o[nt][1] * i0));
        *(float2*)&ob[(size_t)(grow + 8) * Cc + col] =
            make_float2(tf32r(o[nt][2] * i1), tf32r(o[nt][3] * i1));
    }
}

// ---------------------------------------------------------------------------
// Launch
// ---------------------------------------------------------------------------
extern "C" void kernel_launch(void* const* d_in, const int* in_sizes, int n_in,
                              void* d_out, int out_size)
{
    const float* x = nullptr, *Wqkv = nullptr, *Wproj = nullptr, *bproj = nullptr;
    for (int i = 0; i < n_in; i++) {
        switch (in_sizes[i]) {
            case 8388608: x = (const float*)d_in[i]; break;
            case 3145728: Wqkv = (const float*)d_in[i]; break;
            case 1048576: Wproj = (const float*)d_in[i]; break;
            case 1024:    bproj = (const float*)d_in[i]; break;
            default: break;
        }
    }
    float* out = (float*)d_out;

    const int GEMM_SMEM = 3 * 2 * 128 * SA * 4;  // 110592 B
    static bool attr_set = false;
    if (!attr_set) {
        cudaFuncSetAttribute(mm_kernel<3 * Cc, 0>,
                             cudaFuncAttributeMaxDynamicSharedMemorySize, GEMM_SMEM);
        cudaFuncSetAttribute(mm_kernel<Cc, 1>,
                             cudaFuncAttributeMaxDynamicSharedMemorySize, GEMM_SMEM);
        cudaFuncSetAttribute(flash_kernel,
                             cudaFuncAttributeMaxDynamicSharedMemorySize, FLASH_SMEM_BYTES);
        attr_set = true;
    }

    // 0) RNA-round inputs to tf32 grid
    {
        float* gx; float* gw1; float* gw2;
        cudaGetSymbolAddress((void**)&gx,  g_x);
        cudaGetSymbolAddress((void**)&gw1, g_w1);
        cudaGetSymbolAddress((void**)&gw2, g_w2);
        round_kernel<<<(Mrows * Cc / 4 + 255) / 256, 256>>>(x, gx, Mrows * Cc / 4);
        round_kernel<<<(3 * Cc * Cc / 4 + 255) / 256, 256>>>(Wqkv, gw1, 3 * Cc * Cc / 4);
        round_kernel<<<(Cc * Cc / 4 + 255) / 256, 256>>>(Wproj, gw2, Cc * Cc / 4);
    }

    // 1) QKV projection
    mm_kernel<3 * Cc, 0><<<dim3(3 * Cc / 128, Mrows / 128), 256, GEMM_SMEM>>>(nullptr, nullptr);

    // 2) Flash attention
    flash_kernel<<<dim3(Nn / 128, Hh, Bc), 256, FLASH_SMEM_BYTES>>>();

    // 3) Output projection + bias
    mm_kernel<Cc, 1><<<dim3(Cc / 128, Mrows / 128), 256, GEMM_SMEM>>>(bproj, out);
}

// round 4
// speedup vs baseline: 7.5510x; 2.0240x over previous
#include <cuda_runtime.h>
#include <cuda_fp16.h>
#include <cstdint>
#include <cstddef>

#define Bc 4
#define Nn 2048
#define Cc 1024
#define Hh 16
#define Dd 64
#define Mrows (Bc * Nn)   // 8192
#define KDIM  Cc          // 1024

// fp16 scratch
__device__ __half g_qkv[(size_t)3 * Bc * Hh * Nn * Dd];  // [3][B][H][N][D]
__device__ __half g_att[(size_t)Mrows * Cc];             // [B][N][C]
__device__ __half g_x [(size_t)Mrows * Cc];
__device__ __half g_w1[(size_t)3 * Cc * Cc];
__device__ __half g_w2[(size_t)Cc * Cc];

// ---------------------------------------------------------------------------
// helpers
// ---------------------------------------------------------------------------
__device__ __forceinline__ void cp16(void* dst, const void* src) {
    uint32_t d = (uint32_t)__cvta_generic_to_shared(dst);
    asm volatile("cp.async.cg.shared.global [%0], [%1], 16;\n" :: "r"(d), "l"(src));
}
#define CP_COMMIT asm volatile("cp.async.commit_group;\n")
template<int N> __device__ __forceinline__ void cp_wait() {
    asm volatile("cp.async.wait_group %0;\n" :: "n"(N));
}

// fp16 mma m16n8k16, fp32 accumulate
__device__ __forceinline__ void mma_f16(float c[4], const uint32_t a[4], const uint32_t b[2]) {
    asm volatile(
        "mma.sync.aligned.m16n8k16.row.col.f32.f16.f16.f32 "
        "{%0,%1,%2,%3},{%4,%5,%6,%7},{%8,%9},{%0,%1,%2,%3};"
        : "+f"(c[0]), "+f"(c[1]), "+f"(c[2]), "+f"(c[3])
        : "r"(a[0]), "r"(a[1]), "r"(a[2]), "r"(a[3]), "r"(b[0]), "r"(b[1]));
}

__device__ __forceinline__ uint32_t pack2(float lo, float hi) {
    __half2 h = __float22half2_rn(make_float2(lo, hi));
    return *(uint32_t*)&h;
}

// ---------------------------------------------------------------------------
// fp32 -> fp16 conversion of inputs
// ---------------------------------------------------------------------------
__global__ void round_kernel(const float* __restrict__ s, __half* __restrict__ d, int n4) {
    int i = blockIdx.x * blockDim.x + threadIdx.x;
    if (i < n4) {
        float4 v = ((const float4*)s)[i];
        uint32_t lo = pack2(v.x, v.y);
        uint32_t hi = pack2(v.z, v.w);
        ((uint2*)d)[i] = make_uint2(lo, hi);
    }
}

// ---------------------------------------------------------------------------
// fp16 GEMM: out[m,n] = sum_k A[m,k]*W[n,k]. 128x128 tile, BK=32 halfs,
// 3-stage cp.async, 8 warps (4m x 2n), warp tile 32x64, mma m16n8k16.
// MODE 0: A=g_x, W=g_w1 -> scatter fp16 into g_qkv [3][B][H][N][D]
// MODE 1: A=g_att, W=g_w2 -> out = acc + bias (fp32)
// ---------------------------------------------------------------------------
#define SA 40                       // smem row stride in halfs (80B)
#define BKh 32                      // K per stage (halfs)
#define NT_K (KDIM / BKh)           // 32
#define STAGE_HALFS (2 * 128 * SA)  // A + B per stage
#define MM_SMEM_BYTES (3 * STAGE_HALFS * 2)   // 61440

template<int MODE>
__global__ void __launch_bounds__(256, 2) mm_kernel(const float* __restrict__ bias,
                                                    float* __restrict__ out)
{
    extern __shared__ __half smh[];
    const __half* A = (MODE == 0) ? g_x : g_att;
    const __half* W = (MODE == 0) ? g_w1 : g_w2;

    const int bx = blockIdx.x, by = blockIdx.y;
    const int tid = threadIdx.x;
    const int w = tid >> 5, lane = tid & 31;
    const int wm = w & 3, wn = w >> 2;
    const int g = lane >> 2, c = lane & 3;

    float acc[2][8][4];
#pragma unroll
    for (int mt = 0; mt < 2; mt++)
#pragma unroll
        for (int nt = 0; nt < 8; nt++)
#pragma unroll
            for (int j = 0; j < 4; j++) acc[mt][nt][j] = 0.f;

#define LOAD_STAGE(s, k0)                                                        \
    {                                                                            \
        __half* as = smh + ((s)) * STAGE_HALFS;                                  \
        __half* bs = as + 128 * SA;                                              \
        _Pragma("unroll")                                                        \
        for (int i = 0; i < 2; i++) {                                            \
            int id = tid + i * 256;                                              \
            int row = id >> 2, cc = id & 3;                                      \
            cp16(as + row * SA + cc * 8,                                         \
                 A + (size_t)(by * 128 + row) * KDIM + (k0) + cc * 8);           \
            cp16(bs + row * SA + cc * 8,                                         \
                 W + (size_t)(bx * 128 + row) * KDIM + (k0) + cc * 8);           \
        }                                                                        \
    }

    LOAD_STAGE(0, 0); CP_COMMIT;
    LOAD_STAGE(1, BKh); CP_COMMIT;

    for (int t = 0; t < NT_K; t++) {
        cp_wait<1>();
        __syncthreads();
        if (t + 2 < NT_K) LOAD_STAGE((t + 2) % 3, (t + 2) * BKh);
        CP_COMMIT;

        const __half* as = smh + (t % 3) * STAGE_HALFS;
        const __half* bs = as + 128 * SA;
#pragma unroll
        for (int kk = 0; kk < 2; kk++) {
            uint32_t af[2][4];
#pragma unroll
            for (int mt = 0; mt < 2; mt++) {
                const __half* ap = as + (wm * 32 + mt * 16 + g) * SA + kk * 16 + c * 2;
                af[mt][0] = *(const uint32_t*)(ap);
                af[mt][1] = *(const uint32_t*)(ap + 8 * SA);
                af[mt][2] = *(const uint32_t*)(ap + 8);
                af[mt][3] = *(const uint32_t*)(ap + 8 * SA + 8);
            }
#pragma unroll
            for (int nt = 0; nt < 8; nt++) {
                const __half* bp = bs + (wn * 64 + nt * 8 + g) * SA + kk * 16 + c * 2;
                uint32_t bf[2] = { *(const uint32_t*)(bp), *(const uint32_t*)(bp + 8) };
                mma_f16(acc[0][nt], af[0], bf);
                mma_f16(acc[1][nt], af[1], bf);
            }
        }
        __syncthreads();
    }
#undef LOAD_STAGE

    // epilogue: C frag c0c1 = row g cols 2c,2c+1 ; c2c3 = row g+8
#pragma unroll
    for (int mt = 0; mt < 2; mt++) {
#pragma unroll
        for (int i2 = 0; i2 < 2; i2++) {
            const int m = by * 128 + wm * 32 + mt * 16 + g + i2 * 8;
            const int bidx = m >> 11;
            const int row  = m & 2047;
#pragma unroll
            for (int nt = 0; nt < 8; nt++) {
                const int n = bx * 128 + wn * 64 + nt * 8 + 2 * c;
                float v0 = acc[mt][nt][i2 * 2 + 0];
                float v1 = acc[mt][nt][i2 * 2 + 1];
                if (MODE == 0) {
                    const int t3 = n >> 10, rem = n & 1023;
                    const int hh = rem >> 6, d = rem & 63;
                    uint32_t p = pack2(v0, v1);
                    *(uint32_t*)&g_qkv[(((size_t)(t3 * Bc + bidx) * Hh + hh) * Nn + row) * Dd + d] = p;
                } else {
                    float2 bb = *(const float2*)&bias[n];
                    *(float2*)&out[(size_t)m * Cc + n] = make_float2(v0 + bb.x, v1 + bb.y);
                }
            }
        }
    }
}

// ---------------------------------------------------------------------------
// Flash attention, fp16 mma. BQ=128, BK=64, 256 threads (8 warps x 16 q-rows).
// K/V double-buffered cp.async. P stays in registers (C-frag == A-frag map).
// V fragments via ldmatrix.x2.trans.
// ---------------------------------------------------------------------------
#define QS 72   // strides in halfs (144B: 16B-aligned rows, conflict-free frags)
#define KS 72
#define VS 72
#define FLASH_SMEM_BYTES ((128 * QS + 2 * 64 * KS + 2 * 64 * VS) * 2)

__global__ void __launch_bounds__(256, 2) flash_kernel()
{
    extern __shared__ __half smh[];
    __half* Qs = smh;                  // 128 x QS
    __half* Ks = Qs + 128 * QS;        // 2 x 64 x KS
    __half* Vs = Ks + 2 * 64 * KS;     // 2 x 64 x VS

    const int qt = blockIdx.x, h = blockIdx.y, b = blockIdx.z;
    const int tid = threadIdx.x;
    const int w = tid >> 5, lane = tid & 31;
    const int g = lane >> 2, c = lane & 3;

    const __half* qptr = g_qkv + ((size_t)(0 * Bc + b) * Hh + h) * Nn * Dd + (size_t)qt * 128 * Dd;
    const __half* kptr = g_qkv + ((size_t)(1 * Bc + b) * Hh + h) * Nn * Dd;
    const __half* vptr = g_qkv + ((size_t)(2 * Bc + b) * Hh + h) * Nn * Dd;

    // load Q tile (128 x 64 halfs): 1024 chunks of 8 halfs
#pragma unroll
    for (int i = 0; i < 4; i++) {
        int id = tid + i * 256;
        int qr = id >> 3, cc = id & 7;
        cp16(Qs + qr * QS + cc * 8, qptr + (size_t)qr * 64 + cc * 8);
    }

#define KV_LOAD(kt, buf)                                                        \
    {                                                                           \
        _Pragma("unroll")                                                       \
        for (int i = 0; i < 2; i++) {                                           \
            int id = tid + i * 256;                                             \
            int kr = id >> 3, cc = id & 7;                                      \
            cp16(Ks + (buf) * 64 * KS + kr * KS + cc * 8,                       \
                 kptr + (size_t)((kt) * 64 + kr) * 64 + cc * 8);                \
            cp16(Vs + (buf) * 64 * VS + kr * VS + cc * 8,                       \
                 vptr + (size_t)((kt) * 64 + kr) * 64 + cc * 8);                \
        }                                                                       \
    }

    KV_LOAD(0, 0); CP_COMMIT;

    float o[8][4];
#pragma unroll
    for (int nt = 0; nt < 8; nt++)
#pragma unroll
        for (int j = 0; j < 4; j++) o[nt][j] = 0.f;
    float m0 = -1e30f, m1 = -1e30f, l0 = 0.f, l1 = 0.f;
    const float ct = 0.125f * 1.4426950408889634f;  // scale * log2(e)
    const int qrow = w * 16 + g;

    for (int kt = 0; kt < Nn / 64; kt++) {
        if (kt + 1 < Nn / 64) KV_LOAD(kt + 1, (kt + 1) & 1);
        CP_COMMIT;
        cp_wait<1>();
        __syncthreads();

        const __half* Kb = Ks + (kt & 1) * 64 * KS;
        const uint32_t vb = (uint32_t)__cvta_generic_to_shared(Vs + (kt & 1) * 64 * VS);

        // S = Q @ K^T
        float s[8][4];
#pragma unroll
        for (int nt = 0; nt < 8; nt++)
#pragma unroll
            for (int j = 0; j < 4; j++) s[nt][j] = 0.f;

#pragma unroll
        for (int kk = 0; kk < 4; kk++) {
            uint32_t a[4];
            const __half* ap = Qs + qrow * QS + kk * 16 + c * 2;
            a[0] = *(const uint32_t*)(ap);
            a[1] = *(const uint32_t*)(ap + 8 * QS);
            a[2] = *(const uint32_t*)(ap + 8);
            a[3] = *(const uint32_t*)(ap + 8 * QS + 8);
#pragma unroll
            for (int nt = 0; nt < 8; nt++) {
                const __half* bp = Kb + (nt * 8 + g) * KS + kk * 16 + c * 2;
                uint32_t bf[2] = { *(const uint32_t*)(bp), *(const uint32_t*)(bp + 8) };
                mma_f16(s[nt], a, bf);
            }
        }

        // online softmax (rows qrow, qrow+8)
        float mx0 = -1e30f, mx1 = -1e30f;
#pragma unroll
        for (int nt = 0; nt < 8; nt++) {
            mx0 = fmaxf(mx0, fmaxf(s[nt][0], s[nt][1]));
            mx1 = fmaxf(mx1, fmaxf(s[nt][2], s[nt][3]));
        }
        mx0 = fmaxf(mx0, __shfl_xor_sync(0xffffffff, mx0, 1));
        mx0 = fmaxf(mx0, __shfl_xor_sync(0xffffffff, mx0, 2));
        mx1 = fmaxf(mx1, __shfl_xor_sync(0xffffffff, mx1, 1));
        mx1 = fmaxf(mx1, __shfl_xor_sync(0xffffffff, mx1, 2));

        const float nm0 = fmaxf(m0, mx0), nm1 = fmaxf(m1, mx1);
        const float cor0 = exp2f((m0 - nm0) * ct);
        const float cor1 = exp2f((m1 - nm1) * ct);
        m0 = nm0; m1 = nm1;

        float ls0 = 0.f, ls1 = 0.f;
#pragma unroll
        for (int nt = 0; nt < 8; nt++) {
            s[nt][0] = exp2f((s[nt][0] - nm0) * ct);
            s[nt][1] = exp2f((s[nt][1] - nm0) * ct);
            s[nt][2] = exp2f((s[nt][2] - nm1) * ct);
            s[nt][3] = exp2f((s[nt][3] - nm1) * ct);
            ls0 += s[nt][0] + s[nt][1];
            ls1 += s[nt][2] + s[nt][3];
        }
        ls0 += __shfl_xor_sync(0xffffffff, ls0, 1);
        ls0 += __shfl_xor_sync(0xffffffff, ls0, 2);
        ls1 += __shfl_xor_sync(0xffffffff, ls1, 1);
        ls1 += __shfl_xor_sync(0xffffffff, ls1, 2);
        l0 = l0 * cor0 + ls0;
        l1 = l1 * cor1 + ls1;

#pragma unroll
        for (int nt = 0; nt < 8; nt++) {
            o[nt][0] *= cor0; o[nt][1] *= cor0;
            o[nt][2] *= cor1; o[nt][3] *= cor1;
        }

        // O += P @ V  (P A-fragment built in registers from s)
#pragma unroll
        for (int kk = 0; kk < 4; kk++) {
            uint32_t pa[4];
            pa[0] = pack2(s[2 * kk][0],     s[2 * kk][1]);
            pa[1] = pack2(s[2 * kk][2],     s[2 * kk][3]);
            pa[2] = pack2(s[2 * kk + 1][0], s[2 * kk + 1][1]);
            pa[3] = pack2(s[2 * kk + 1][2], s[2 * kk + 1][3]);
            const uint32_t vrow = vb + (uint32_t)(((kk * 16 + (lane & 15)) * VS) * 2);
#pragma unroll
            for (int nt = 0; nt < 8; nt++) {
                uint32_t bf[2];
                asm volatile("ldmatrix.sync.aligned.m8n8.x2.trans.shared.b16 {%0,%1}, [%2];"
                             : "=r"(bf[0]), "=r"(bf[1]) : "r"(vrow + nt * 16));
                mma_f16(o[nt], pa, bf);
            }
        }
        __syncthreads();  // protect K/V buffers before next overwrite
    }
#undef KV_LOAD

    // finalize: normalize, fp16 store to g_att
    const float i0 = 1.f / l0, i1 = 1.f / l1;
    const int grow = qt * 128 + qrow;
    __half* ob = g_att + ((size_t)b * Nn) * Cc + (size_t)h * 64;
#pragma unroll
    for (int nt = 0; nt < 8; nt++) {
        const int col = nt * 8 + 2 * c;
        *(uint32_t*)&ob[(size_t)grow * Cc + col] = pack2(o[nt][0] * i0, o[nt][1] * i0);
        *(uint32_t*)&ob[(size_t)(grow + 8) * Cc + col] = pack2(o[nt][2] * i1, o[nt][3] * i1);
    }
}

// ---------------------------------------------------------------------------
// Launch
// ---------------------------------------------------------------------------
extern "C" void kernel_launch(void* const* d_in, const int* in_sizes, int n_in,
                              void* d_out, int out_size)
{
    const float* x = nullptr, *Wqkv = nullptr, *Wproj = nullptr, *bproj = nullptr;
    for (int i = 0; i < n_in; i++) {
        switch (in_sizes[i]) {
            case 8388608: x = (const float*)d_in[i]; break;
            case 3145728: Wqkv = (const float*)d_in[i]; break;
            case 1048576: Wproj = (const float*)d_in[i]; break;
            case 1024:    bproj = (const float*)d_in[i]; break;
            default: break;
        }
    }
    float* out = (float*)d_out;

    static bool attr_set = false;
    if (!attr_set) {
        cudaFuncSetAttribute(mm_kernel<0>,
                             cudaFuncAttributeMaxDynamicSharedMemorySize, MM_SMEM_BYTES);
        cudaFuncSetAttribute(mm_kernel<1>,
                             cudaFuncAttributeMaxDynamicSharedMemorySize, MM_SMEM_BYTES);
        cudaFuncSetAttribute(flash_kernel,
                             cudaFuncAttributeMaxDynamicSharedMemorySize, FLASH_SMEM_BYTES);
        attr_set = true;
    }

    // 0) fp32 -> fp16 conversion of inputs
    {
        __half* gx; __half* gw1; __half* gw2;
        cudaGetSymbolAddress((void**)&gx,  g_x);
        cudaGetSymbolAddress((void**)&gw1, g_w1);
        cudaGetSymbolAddress((void**)&gw2, g_w2);
        round_kernel<<<(Mrows * Cc / 4 + 255) / 256, 256>>>(x, gx, Mrows * Cc / 4);
        round_kernel<<<(3 * Cc * Cc / 4 + 255) / 256, 256>>>(Wqkv, gw1, 3 * Cc * Cc / 4);
        round_kernel<<<(Cc * Cc / 4 + 255) / 256, 256>>>(Wproj, gw2, Cc * Cc / 4);
    }

    // 1) QKV projection
    mm_kernel<0><<<dim3(3 * Cc / 128, Mrows / 128), 256, MM_SMEM_BYTES>>>(nullptr, nullptr);

    // 2) Flash attention
    flash_kernel<<<dim3(Nn / 128, Hh, Bc), 256, FLASH_SMEM_BYTES>>>();

    // 3) Output projection + bias
    mm_kernel<1><<<dim3(Cc / 128, Mrows / 128), 256, MM_SMEM_BYTES>>>(bproj, out);
}

// round 5
// speedup vs baseline: 8.4396x; 1.1177x over previous
#include <cuda_runtime.h>
#include <cuda_fp16.h>
#include <cstdint>
#include <cstddef>

#define Bc 4
#define Nn 2048
#define Cc 1024
#define Hh 16
#define Dd 64
#define Mrows (Bc * Nn)   // 8192
#define KDIM  Cc          // 1024

// fp16 scratch
__device__ __half g_qkv[(size_t)3 * Bc * Hh * Nn * Dd];  // [3][B][H][N][D]
__device__ __half g_att[(size_t)Mrows * Cc];             // [B][N][C]
__device__ __half g_x [(size_t)Mrows * Cc];
__device__ __half g_w1[(size_t)3 * Cc * Cc];
__device__ __half g_w2[(size_t)Cc * Cc];

// ---------------------------------------------------------------------------
// helpers
// ---------------------------------------------------------------------------
__device__ __forceinline__ void cp16s(uint32_t dst, const void* src) {
    asm volatile("cp.async.cg.shared.global [%0], [%1], 16;\n" :: "r"(dst), "l"(src));
}
#define CP_COMMIT asm volatile("cp.async.commit_group;\n")
template<int N> __device__ __forceinline__ void cp_wait() {
    asm volatile("cp.async.wait_group %0;\n" :: "n"(N));
}

__device__ __forceinline__ void mma_f16(float c[4], const uint32_t a[4], const uint32_t b[2]) {
    asm volatile(
        "mma.sync.aligned.m16n8k16.row.col.f32.f16.f16.f32 "
        "{%0,%1,%2,%3},{%4,%5,%6,%7},{%8,%9},{%0,%1,%2,%3};"
        : "+f"(c[0]), "+f"(c[1]), "+f"(c[2]), "+f"(c[3])
        : "r"(a[0]), "r"(a[1]), "r"(a[2]), "r"(a[3]), "r"(b[0]), "r"(b[1]));
}

#define LDM_X4(r0, r1, r2, r3, addr)                                             \
    asm volatile("ldmatrix.sync.aligned.m8n8.x4.shared.b16 {%0,%1,%2,%3}, [%4];" \
                 : "=r"(r0), "=r"(r1), "=r"(r2), "=r"(r3) : "r"(addr))

__device__ __forceinline__ uint32_t pack2(float lo, float hi) {
    __half2 h = __float22half2_rn(make_float2(lo, hi));
    return *(uint32_t*)&h;
}

// ---------------------------------------------------------------------------
// fp32 -> fp16 conversion of inputs
// ---------------------------------------------------------------------------
__global__ void round_kernel(const float* __restrict__ s, __half* __restrict__ d, int n4) {
    int i = blockIdx.x * blockDim.x + threadIdx.x;
    if (i < n4) {
        float4 v = ((const float4*)s)[i];
        ((uint2*)d)[i] = make_uint2(pack2(v.x, v.y), pack2(v.z, v.w));
    }
}

// ---------------------------------------------------------------------------
// fp16 GEMM: out[m,n] = sum_k A[m,k]*W[n,k]. 128x128 tile, BK=64 halfs,
// 3-stage cp.async ring (1 sync/stage), ldmatrix.x4 fragment loads,
// 8 warps (4m x 2n), warp tile 32x64, mma m16n8k16.
// MODE 0 -> scatter fp16 into g_qkv [3][B][H][N][D]; MODE 1 -> out = acc + bias
// ---------------------------------------------------------------------------
#define SA 72                            // smem row stride in halfs (144B)
#define BKh 64                           // K per stage (halfs)
#define NT_K (KDIM / BKh)                // 16
#define A_STAGE_BYTES (128 * SA * 2)     // 18432
#define STAGE_BYTES (2 * A_STAGE_BYTES)  // 36864
#define MM_SMEM_BYTES (3 * STAGE_BYTES)  // 110592

template<int MODE>
__global__ void __launch_bounds__(256, 2) mm_kernel(const float* __restrict__ bias,
                                                    float* __restrict__ out)
{
    extern __shared__ __half smh[];
    const uint32_t smem_u = (uint32_t)__cvta_generic_to_shared(smh);
    const __half* A = (MODE == 0) ? g_x : g_att;
    const __half* W = (MODE == 0) ? g_w1 : g_w2;

    const int bx = blockIdx.x, by = blockIdx.y;
    const int tid = threadIdx.x;
    const int w = tid >> 5, lane = tid & 31;
    const int wm = w & 3, wn = w >> 2;
    const int g = lane >> 2, c = lane & 3;

    float acc[2][8][4];
#pragma unroll
    for (int mt = 0; mt < 2; mt++)
#pragma unroll
        for (int nt = 0; nt < 8; nt++)
#pragma unroll
            for (int j = 0; j < 4; j++) acc[mt][nt][j] = 0.f;

    // per-thread load pattern: row = id>>3 (0..127), k-chunk = (id&7)*8
#define LOAD_STAGE(s, k0)                                                        \
    {                                                                            \
        const uint32_t au = smem_u + ((s)) * STAGE_BYTES;                        \
        const uint32_t bu = au + A_STAGE_BYTES;                                  \
        _Pragma("unroll")                                                        \
        for (int i = 0; i < 4; i++) {                                            \
            int id = tid + i * 256;                                              \
            int row = id >> 3, cc = id & 7;                                      \
            cp16s(au + (uint32_t)((row * SA + cc * 8) * 2),                      \
                  A + (size_t)(by * 128 + row) * KDIM + (k0) + cc * 8);          \
            cp16s(bu + (uint32_t)((row * SA + cc * 8) * 2),                      \
                  W + (size_t)(bx * 128 + row) * KDIM + (k0) + cc * 8);          \
        }                                                                        \
    }

    LOAD_STAGE(0, 0); CP_COMMIT;
    LOAD_STAGE(1, BKh); CP_COMMIT;

    // ldmatrix lane addressing (precomputed offsets in halfs)
    const int a_row = wm * 32 + (lane & 15);          // + mt*16
    const int a_koff = (lane >> 4) << 3;              // 0 or 8
    const int b_row = wn * 64 + (lane & 7) + ((lane >> 4) << 3);  // + p*16
    const int b_koff = ((lane >> 3) & 1) << 3;        // 0 or 8

    for (int t = 0; t < NT_K; t++) {
        cp_wait<1>();
        __syncthreads();
        if (t + 2 < NT_K) LOAD_STAGE((t + 2) % 3, (t + 2) * BKh);
        CP_COMMIT;

        const uint32_t au = smem_u + (t % 3) * STAGE_BYTES;
        const uint32_t bu = au + A_STAGE_BYTES;
#pragma unroll
        for (int kk = 0; kk < 4; kk++) {                 // 4 x k16 within BK=64
            uint32_t af[2][4];
#pragma unroll
            for (int mt = 0; mt < 2; mt++) {
                uint32_t addr = au + (uint32_t)((((a_row + mt * 16) * SA) + kk * 16 + a_koff) * 2);
                LDM_X4(af[mt][0], af[mt][1], af[mt][2], af[mt][3], addr);
            }
            uint32_t bq[4][4];
#pragma unroll
            for (int p = 0; p < 4; p++) {
                uint32_t addr = bu + (uint32_t)((((b_row + p * 16) * SA) + kk * 16 + b_koff) * 2);
                LDM_X4(bq[p][0], bq[p][1], bq[p][2], bq[p][3], addr);
            }
#pragma unroll
            for (int p = 0; p < 4; p++) {
                mma_f16(acc[0][2 * p],     af[0], &bq[p][0]);
                mma_f16(acc[0][2 * p + 1], af[0], &bq[p][2]);
                mma_f16(acc[1][2 * p],     af[1], &bq[p][0]);
                mma_f16(acc[1][2 * p + 1], af[1], &bq[p][2]);
            }
        }
    }
#undef LOAD_STAGE

    // epilogue: C frag c0c1 = row g cols 2c,2c+1 ; c2c3 = row g+8
#pragma unroll
    for (int mt = 0; mt < 2; mt++) {
#pragma unroll
        for (int i2 = 0; i2 < 2; i2++) {
            const int m = by * 128 + wm * 32 + mt * 16 + g + i2 * 8;
            const int bidx = m >> 11;
            const int row  = m & 2047;
#pragma unroll
            for (int nt = 0; nt < 8; nt++) {
                const int n = bx * 128 + wn * 64 + nt * 8 + 2 * c;
                float v0 = acc[mt][nt][i2 * 2 + 0];
                float v1 = acc[mt][nt][i2 * 2 + 1];
                if (MODE == 0) {
                    const int t3 = n >> 10, rem = n & 1023;
                    const int hh = rem >> 6, d = rem & 63;
                    *(uint32_t*)&g_qkv[(((size_t)(t3 * Bc + bidx) * Hh + hh) * Nn + row) * Dd + d] =
                        pack2(v0, v1);
                } else {
                    float2 bb = *(const float2*)&bias[n];
                    *(float2*)&out[(size_t)m * Cc + n] = make_float2(v0 + bb.x, v1 + bb.y);
                }
            }
        }
    }
}

// ---------------------------------------------------------------------------
// Flash attention, fp16 mma. BQ=128, BK=64, 256 threads (8 warps x 16 q-rows).
// ldmatrix.x4 Q/K frags, ldmatrix.x2.trans V frags, P stays in registers.
// Double-buffered K/V, 1 sync per tile.
// ---------------------------------------------------------------------------
#define QS 72
#define KS 72
#define VS 72
#define FLASH_SMEM_BYTES ((128 * QS + 2 * 64 * KS + 2 * 64 * VS) * 2)

__global__ void __launch_bounds__(256, 2) flash_kernel()
{
    extern __shared__ __half smh[];
    const uint32_t smem_u = (uint32_t)__cvta_generic_to_shared(smh);
    const uint32_t qs_u = smem_u;
    const uint32_t ks_u = qs_u + 128 * QS * 2;
    const uint32_t vs_u = ks_u + 2 * 64 * KS * 2;

    const int qt = blockIdx.x, h = blockIdx.y, b = blockIdx.z;
    const int tid = threadIdx.x;
    const int w = tid >> 5, lane = tid & 31;
    const int g = lane >> 2, c = lane & 3;

    const __half* qptr = g_qkv + ((size_t)(0 * Bc + b) * Hh + h) * Nn * Dd + (size_t)qt * 128 * Dd;
    const __half* kptr = g_qkv + ((size_t)(1 * Bc + b) * Hh + h) * Nn * Dd;
    const __half* vptr = g_qkv + ((size_t)(2 * Bc + b) * Hh + h) * Nn * Dd;

    // load Q tile (128 x 64): 1024 chunks of 8 halfs
#pragma unroll
    for (int i = 0; i < 4; i++) {
        int id = tid + i * 256;
        int qr = id >> 3, cc = id & 7;
        cp16s(qs_u + (uint32_t)((qr * QS + cc * 8) * 2), qptr + (size_t)qr * 64 + cc * 8);
    }

#define KV_LOAD(kt, buf)                                                        \
    {                                                                           \
        _Pragma("unroll")                                                       \
        for (int i = 0; i < 2; i++) {                                           \
            int id = tid + i * 256;                                             \
            int kr = id >> 3, cc = id & 7;                                      \
            cp16s(ks_u + (uint32_t)(((buf) * 64 * KS + kr * KS + cc * 8) * 2),  \
                  kptr + (size_t)((kt) * 64 + kr) * 64 + cc * 8);               \
            cp16s(vs_u + (uint32_t)(((buf) * 64 * VS + kr * VS + cc * 8) * 2),  \
                  vptr + (size_t)((kt) * 64 + kr) * 64 + cc * 8);               \
        }                                                                       \
    }

    KV_LOAD(0, 0); CP_COMMIT;

    float o[8][4];
#pragma unroll
    for (int nt = 0; nt < 8; nt++)
#pragma unroll
        for (int j = 0; j < 4; j++) o[nt][j] = 0.f;
    float m0 = -1e30f, m1 = -1e30f, l0 = 0.f, l1 = 0.f;
    const float ct = 0.125f * 1.4426950408889634f;  // scale * log2(e)

    // ldmatrix lane offsets
    const int q_row = w * 16 + (lane & 15);
    const int q_koff = (lane >> 4) << 3;
    const int k_row = (lane & 7) + ((lane >> 4) << 3);   // + p*16
    const int k_koff = ((lane >> 3) & 1) << 3;

    for (int kt = 0; kt < Nn / 64; kt++) {
        cp_wait<0>();
        __syncthreads();
        if (kt + 1 < Nn / 64) KV_LOAD(kt + 1, (kt + 1) & 1);
        CP_COMMIT;

        const uint32_t kb_u = ks_u + (kt & 1) * 64 * KS * 2;
        const uint32_t vb_u = vs_u + (kt & 1) * 64 * VS * 2;

        // S = Q @ K^T
        float s[8][4];
#pragma unroll
        for (int nt = 0; nt < 8; nt++)
#pragma unroll
            for (int j = 0; j < 4; j++) s[nt][j] = 0.f;

#pragma unroll
        for (int kk = 0; kk < 4; kk++) {
            uint32_t af[4];
            LDM_X4(af[0], af[1], af[2], af[3],
                   qs_u + (uint32_t)(((q_row * QS) + kk * 16 + q_koff) * 2));
#pragma unroll
            for (int p = 0; p < 4; p++) {
                uint32_t bq[4];
                LDM_X4(bq[0], bq[1], bq[2], bq[3],
                       kb_u + (uint32_t)((((k_row + p * 16) * KS) + kk * 16 + k_koff) * 2));
                mma_f16(s[2 * p],     af, &bq[0]);
                mma_f16(s[2 * p + 1], af, &bq[2]);
            }
        }

        // online softmax (rows q_row base: g and g+8)
        float mx0 = -1e30f, mx1 = -1e30f;
#pragma unroll
        for (int nt = 0; nt < 8; nt++) {
            mx0 = fmaxf(mx0, fmaxf(s[nt][0], s[nt][1]));
            mx1 = fmaxf(mx1, fmaxf(s[nt][2], s[nt][3]));
        }
        mx0 = fmaxf(mx0, __shfl_xor_sync(0xffffffff, mx0, 1));
        mx0 = fmaxf(mx0, __shfl_xor_sync(0xffffffff, mx0, 2));
        mx1 = fmaxf(mx1, __shfl_xor_sync(0xffffffff, mx1, 1));
        mx1 = fmaxf(mx1, __shfl_xor_sync(0xffffffff, mx1, 2));

        const float nm0 = fmaxf(m0, mx0), nm1 = fmaxf(m1, mx1);
        const float cor0 = exp2f((m0 - nm0) * ct);
        const float cor1 = exp2f((m1 - nm1) * ct);
        m0 = nm0; m1 = nm1;

        float ls0 = 0.f, ls1 = 0.f;
#pragma unroll
        for (int nt = 0; nt < 8; nt++) {
            s[nt][0] = exp2f((s[nt][0] - nm0) * ct);
            s[nt][1] = exp2f((s[nt][1] - nm0) * ct);
            s[nt][2] = exp2f((s[nt][2] - nm1) * ct);
            s[nt][3] = exp2f((s[nt][3] - nm1) * ct);
            ls0 += s[nt][0] + s[nt][1];
            ls1 += s[nt][2] + s[nt][3];
        }
        ls0 += __shfl_xor_sync(0xffffffff, ls0, 1);
        ls0 += __shfl_xor_sync(0xffffffff, ls0, 2);
        ls1 += __shfl_xor_sync(0xffffffff, ls1, 1);
        ls1 += __shfl_xor_sync(0xffffffff, ls1, 2);
        l0 = l0 * cor0 + ls0;
        l1 = l1 * cor1 + ls1;

#pragma unroll
        for (int nt = 0; nt < 8; nt++) {
            o[nt][0] *= cor0; o[nt][1] *= cor0;
            o[nt][2] *= cor1; o[nt][3] *= cor1;
        }

        // O += P @ V  (P A-fragment built in registers)
#pragma unroll
        for (int kk = 0; kk < 4; kk++) {
            uint32_t pa[4];
            pa[0] = pack2(s[2 * kk][0],     s[2 * kk][1]);
            pa[1] = pack2(s[2 * kk][2],     s[2 * kk][3]);
            pa[2] = pack2(s[2 * kk + 1][0], s[2 * kk + 1][1]);
            pa[3] = pack2(s[2 * kk + 1][2], s[2 * kk + 1][3]);
            const uint32_t vrow = vb_u + (uint32_t)(((kk * 16 + (lane & 15)) * VS) * 2);
#pragma unroll
            for (int nt = 0; nt < 8; nt++) {
                uint32_t bf[2];
                asm volatile("ldmatrix.sync.aligned.m8n8.x2.trans.shared.b16 {%0,%1}, [%2];"
                             : "=r"(bf[0]), "=r"(bf[1]) : "r"(vrow + nt * 16));
                mma_f16(o[nt], pa, bf);
            }
        }
    }
#undef KV_LOAD

    // finalize: normalize, fp16 store to g_att
    const float i0 = 1.f / l0, i1 = 1.f / l1;
    const int grow = qt * 128 + w * 16 + g;
    __half* ob = g_att + ((size_t)b * Nn) * Cc + (size_t)h * 64;
#pragma unroll
    for (int nt = 0; nt < 8; nt++) {
        const int col = nt * 8 + 2 * c;
        *(uint32_t*)&ob[(size_t)grow * Cc + col] = pack2(o[nt][0] * i0, o[nt][1] * i0);
        *(uint32_t*)&ob[(size_t)(grow + 8) * Cc + col] = pack2(o[nt][2] * i1, o[nt][3] * i1);
    }
}

// ---------------------------------------------------------------------------
// Launch
// ---------------------------------------------------------------------------
extern "C" void kernel_launch(void* const* d_in, const int* in_sizes, int n_in,
                              void* d_out, int out_size)
{
    const float* x = nullptr, *Wqkv = nullptr, *Wproj = nullptr, *bproj = nullptr;
    for (int i = 0; i < n_in; i++) {
        switch (in_sizes[i]) {
            case 8388608: x = (const float*)d_in[i]; break;
            case 3145728: Wqkv = (const float*)d_in[i]; break;
            case 1048576: Wproj = (const float*)d_in[i]; break;
            case 1024:    bproj = (const float*)d_in[i]; break;
            default: break;
        }
    }
    float* out = (float*)d_out;

    static bool attr_set = false;
    if (!attr_set) {
        cudaFuncSetAttribute(mm_kernel<0>,
                             cudaFuncAttributeMaxDynamicSharedMemorySize, MM_SMEM_BYTES);
        cudaFuncSetAttribute(mm_kernel<1>,
                             cudaFuncAttributeMaxDynamicSharedMemorySize, MM_SMEM_BYTES);
        cudaFuncSetAttribute(flash_kernel,
                             cudaFuncAttributeMaxDynamicSharedMemorySize, FLASH_SMEM_BYTES);
        attr_set = true;
    }

    // 0) fp32 -> fp16 conversion of inputs
    {
        __half* gx; __half* gw1; __half* gw2;
        cudaGetSymbolAddress((void**)&gx,  g_x);
        cudaGetSymbolAddress((void**)&gw1, g_w1);
        cudaGetSymbolAddress((void**)&gw2, g_w2);
        round_kernel<<<(Mrows * Cc / 4 + 255) / 256, 256>>>(x, gx, Mrows * Cc / 4);
        round_kernel<<<(3 * Cc * Cc / 4 + 255) / 256, 256>>>(Wqkv, gw1, 3 * Cc * Cc / 4);
        round_kernel<<<(Cc * Cc / 4 + 255) / 256, 256>>>(Wproj, gw2, Cc * Cc / 4);
    }

    // 1) QKV projection
    mm_kernel<0><<<dim3(3 * Cc / 128, Mrows / 128), 256, MM_SMEM_BYTES>>>(nullptr, nullptr);

    // 2) Flash attention
    flash_kernel<<<dim3(Nn / 128, Hh, Bc), 256, FLASH_SMEM_BYTES>>>();

    // 3) Output projection + bias
    mm_kernel<1><<<dim3(Cc / 128, Mrows / 128), 256, MM_SMEM_BYTES>>>(bproj, out);
}